// round 13
// baseline (speedup 1.0000x reference)
#include <cuda_runtime.h>
#include <cuda_bf16.h>
#include <cstdint>

typedef unsigned long long ull;

#define E_DIM 128
#define NPG   32
#define TPB   256
#define PAD   132           // fp32 row stride in attention smem (floats)
#define XSB   272           // bf16 tile row stride (bytes)
#define XH64  17408         // bytes per 64-row bf16 tile (64*272)
#define ATILE 34816         // bytes per 64-row hi+lo A tile
#define WHALF 34816         // bytes per 128-row bf16 tile (128*272)
#define WB    69632         // bytes per weight (hi+lo)

// GEMM kernels' smem layout
#define OFF_W    0          // 69632: weight hi/lo
#define OFF_X    69632      // 34816: A tile hi/lo
#define OFF_BIAS 104448     // 128 floats
#define SMEM_GEMM 105472

// attention kernel smem layout (fp32, stride PAD)
#define AOFF_Q   0
#define AOFF_K   16896
#define AOFF_V   33792
#define SMEM_ATTN 50688

__device__ __align__(1024) unsigned char g_wconv[4 * WB];
__device__ __align__(16) float g_qs[4194304];                    // 32768 x 128
__device__ __align__(16) float g_ks[4194304];
__device__ __align__(16) float g_vs[4194304];
__device__ __align__(1024) unsigned char g_ao[512 * ATILE];      // pre-tiled attn-out

// ---------- helpers ----------
__device__ __forceinline__ uint32_t s2u(const void* p) {
    uint32_t a;
    asm("{ .reg .u64 t; cvta.to.shared.u64 t, %1; cvt.u32.u64 %0, t; }" : "=r"(a) : "l"(p));
    return a;
}
__device__ __forceinline__ ull pack2(float lo, float hi) {
    ull r; asm("mov.b64 %0, {%1, %2};" : "=l"(r) : "f"(lo), "f"(hi)); return r;
}
__device__ __forceinline__ void unpack2(ull p, float& lo, float& hi) {
    asm("mov.b64 {%0, %1}, %2;" : "=f"(lo), "=f"(hi) : "l"(p));
}
__device__ __forceinline__ void ffma2(ull& d, ull a, ull b) {
    asm("fma.rn.f32x2 %0, %1, %2, %0;" : "+l"(d) : "l"(a), "l"(b));
}
__device__ __forceinline__ ull pack4bf(__nv_bfloat16 a, __nv_bfloat16 b,
                                       __nv_bfloat16 c, __nv_bfloat16 d) {
    uint32_t lo = ((uint32_t)__bfloat16_as_ushort(b) << 16) | __bfloat16_as_ushort(a);
    uint32_t hi = ((uint32_t)__bfloat16_as_ushort(d) << 16) | __bfloat16_as_ushort(c);
    return ((ull)hi << 32) | lo;
}
__device__ __forceinline__ void split4(float4 x, ull& hiw, ull& low) {
    __nv_bfloat16 h0 = __float2bfloat16(x.x), h1 = __float2bfloat16(x.y),
                  h2 = __float2bfloat16(x.z), h3 = __float2bfloat16(x.w);
    __nv_bfloat16 l0 = __float2bfloat16(x.x - __bfloat162float(h0));
    __nv_bfloat16 l1 = __float2bfloat16(x.y - __bfloat162float(h1));
    __nv_bfloat16 l2 = __float2bfloat16(x.z - __bfloat162float(h2));
    __nv_bfloat16 l3 = __float2bfloat16(x.w - __bfloat162float(h3));
    hiw = pack4bf(h0, h1, h2, h3);
    low = pack4bf(l0, l1, l2, l3);
}
__device__ __forceinline__ void ldsm4(uint32_t& r0, uint32_t& r1, uint32_t& r2,
                                      uint32_t& r3, uint32_t a) {
    asm volatile("ldmatrix.sync.aligned.m8n8.x4.shared.b16 {%0,%1,%2,%3}, [%4];"
                 : "=r"(r0), "=r"(r1), "=r"(r2), "=r"(r3) : "r"(a));
}
__device__ __forceinline__ void mma_bf16(float* c, const uint32_t* a,
                                         uint32_t b0, uint32_t b1) {
    asm volatile(
        "mma.sync.aligned.m16n8k16.row.col.f32.bf16.bf16.f32 "
        "{%0,%1,%2,%3}, {%4,%5,%6,%7}, {%8,%9}, {%0,%1,%2,%3};"
        : "+f"(c[0]), "+f"(c[1]), "+f"(c[2]), "+f"(c[3])
        : "r"(a[0]), "r"(a[1]), "r"(a[2]), "r"(a[3]), "r"(b0), "r"(b1));
}
__device__ __forceinline__ void cp16(uint32_t smem, const void* g) {
    asm volatile("cp.async.ca.shared.global [%0], [%1], 16;" :: "r"(smem), "l"(g) : "memory");
}
#define CP_COMMIT() asm volatile("cp.async.commit_group;" ::: "memory")
#define CP_WAIT0()  asm volatile("cp.async.wait_group 0;" ::: "memory")

// ---------- building blocks ----------
// X (64x128 f32, gmem) -> hi/lo bf16 tiles at OFF_X (256 threads)
__device__ __forceinline__ void convert_X(const float* __restrict__ gx, char* raw, int tid) {
    const int row  = tid >> 2;           // 0..63
    const int colb = (tid & 3) * 32;
#pragma unroll
    for (int i = 0; i < 8; i++) {
        const int col = colb + i * 4;
        float4 x = *reinterpret_cast<const float4*>(gx + row * E_DIM + col);
        ull hw, lw; split4(x, hw, lw);
        *(ull*)(raw + OFF_X + row * XSB + col * 2)        = hw;
        *(ull*)(raw + OFF_X + XH64 + row * XSB + col * 2) = lw;
    }
}
// async full weight copy: 4352 x 16B (256 threads x 17)
__device__ __forceinline__ void copy_W_async(int wsel, uint32_t sb, int tid) {
    const char* s = reinterpret_cast<const char*>(g_wconv) + wsel * WB;
    const uint32_t d = sb + OFF_W;
#pragma unroll
    for (int i = 0; i < 17; i++)
        cp16(d + (i * TPB + tid) * 16, s + (size_t)(i * TPB + tid) * 16);
    CP_COMMIT();
}

// 64x128 output, K=128, 3-split bf16 MMA, 16x64 warp tile (8 warps: 4x2 grid).
__device__ __forceinline__ void gemm8(char* raw, float acc[8][4], int w, int l) {
    const int wm = w >> 1, wn = w & 1;
    const uint32_t sb = s2u(raw);
#pragma unroll
    for (int s = 0; s < 8; s++)
#pragma unroll
        for (int i = 0; i < 4; i++) acc[s][i] = 0.f;
    const uint32_t aBase = sb + OFF_X + (wm * 16 + (l & 15)) * XSB + (l >> 4) * 16;
    const uint32_t bBase = sb + OFF_W +
        (wn * 64 + (l & 7) + ((l >> 4) & 1) * 8) * XSB + ((l >> 3) & 1) * 16;
#pragma unroll
    for (int k8 = 0; k8 < 8; k8++) {
        uint32_t ah[4], al[4];
        ldsm4(ah[0], ah[1], ah[2], ah[3], aBase + k8 * 32);
        ldsm4(al[0], al[1], al[2], al[3], aBase + XH64 + k8 * 32);
        uint32_t bh[16], bl[16];
#pragma unroll
        for (int sp = 0; sp < 4; sp++) {
            ldsm4(bh[4 * sp], bh[4 * sp + 1], bh[4 * sp + 2], bh[4 * sp + 3],
                  bBase + sp * 16 * XSB + k8 * 32);
            ldsm4(bl[4 * sp], bl[4 * sp + 1], bl[4 * sp + 2], bl[4 * sp + 3],
                  bBase + WHALF + sp * 16 * XSB + k8 * 32);
        }
#pragma unroll
        for (int sub = 0; sub < 8; sub++)
            mma_bf16(acc[sub], ah, bh[2 * sub], bh[2 * sub + 1]);   // hi*hi
#pragma unroll
        for (int sub = 0; sub < 8; sub++)
            mma_bf16(acc[sub], ah, bl[2 * sub], bl[2 * sub + 1]);   // hi*lo
#pragma unroll
        for (int sub = 0; sub < 8; sub++)
            mma_bf16(acc[sub], al, bh[2 * sub], bh[2 * sub + 1]);   // lo*hi
    }
}
__device__ __forceinline__ void epilogue8(const float acc[8][4], const float* bias,
                                          float scale, float* dst, int dstride,
                                          int w, int l) {
    const int wm = w >> 1, wn = w & 1;
    const int r0 = wm * 16 + (l >> 2);
#pragma unroll
    for (int sub = 0; sub < 8; sub++) {
        const int cb = wn * 64 + sub * 8 + (l & 3) * 2;
        float2 v;
        v.x = (acc[sub][0] + bias[cb]) * scale;
        v.y = (acc[sub][1] + bias[cb + 1]) * scale;
        *reinterpret_cast<float2*>(dst + r0 * dstride + cb) = v;
        v.x = (acc[sub][2] + bias[cb]) * scale;
        v.y = (acc[sub][3] + bias[cb + 1]) * scale;
        *reinterpret_cast<float2*>(dst + (r0 + 8) * dstride + cb) = v;
    }
}

// ---------- kernel 0: weights f32 -> bf16 hi/lo tiles ----------
extern "C" __global__ void wconv_kernel(const float* __restrict__ wq,
                                        const float* __restrict__ wk,
                                        const float* __restrict__ wv,
                                        const float* __restrict__ wo) {
    const int idx = (blockIdx.x * blockDim.x + threadIdx.x) * 4;
    const int wsel = idx >> 14;
    const float* W = (wsel == 0) ? wq : (wsel == 1) ? wk : (wsel == 2) ? wv : wo;
    const int rem = idx & 16383;
    const int c = rem >> 7, k = rem & 127;
    float4 x = *reinterpret_cast<const float4*>(W + c * 128 + k);
    ull hw, lw; split4(x, hw, lw);
    *(ull*)(g_wconv + wsel * WB + c * XSB + k * 2)         = hw;
    *(ull*)(g_wconv + wsel * WB + WHALF + c * XSB + k * 2) = lw;
}

// ---------- kernel 1: QKV projections, CTA = (64-row tile, which) ----------
extern "C" __global__ void __launch_bounds__(TPB, 2)
proj_kernel(const float* __restrict__ query, const float* __restrict__ key,
            const float* __restrict__ value,
            const float* __restrict__ bq, const float* __restrict__ bk,
            const float* __restrict__ bv)
{
    extern __shared__ char raw[];
    const int tid = threadIdx.x;
    const int w = tid >> 5, l = tid & 31;
    const int which = blockIdx.y;
    const size_t base = (size_t)blockIdx.x * 64 * E_DIM;
    const uint32_t sb = s2u(raw);
    float* bias_s = reinterpret_cast<float*>(raw + OFF_BIAS);

    const float* gx = (which == 0) ? query : (which == 1) ? key : value;
    const float* gb = (which == 0) ? bq : (which == 1) ? bk : bv;
    float* dst = ((which == 0) ? g_qs : (which == 1) ? g_ks : g_vs) + base;

    copy_W_async(which, sb, tid);
    if (tid < 128) bias_s[tid] = gb[tid];
    convert_X(gx + base, raw, tid);
    CP_WAIT0();
    __syncthreads();

    float acc[8][4];
    gemm8(raw, acc, w, l);
    epilogue8(acc, bias_s, (which == 0) ? 0.25f : 1.0f, dst, E_DIM, w, l);
}

// ---------- kernel 2: attention, CTA = graph, warp = head ----------
extern "C" __global__ void __launch_bounds__(TPB)
attn_kernel()
{
    extern __shared__ char raw[];
    const int tid = threadIdx.x;
    const int w = tid >> 5, l = tid & 31;
    const int g = blockIdx.x;
    const uint32_t sb = s2u(raw);
    const size_t gbase = (size_t)g * NPG * E_DIM;   // float offset

    // stage Q,K,V (32x128 f32 each = 1024 x 16B chunks each) into smem, stride PAD
#pragma unroll
    for (int i = 0; i < 4; i++) {
        const int idx = i * TPB + tid;           // 0..1023
        const int row = idx >> 5;                // 0..31
        const int j   = idx & 31;                // 0..31 (16B chunks per 512B row)
        const uint32_t doff = row * (PAD * 4) + j * 16;
        const size_t soff = (size_t)row * E_DIM + j * 4;
        cp16(sb + AOFF_Q + doff, g_qs + gbase + soff);
        cp16(sb + AOFF_K + doff, g_ks + gbase + soff);
        cp16(sb + AOFF_V + doff, g_vs + gbase + soff);
    }
    CP_COMMIT();
    CP_WAIT0();
    __syncthreads();

    const float* Qs = reinterpret_cast<const float*>(raw + AOFF_Q);
    const float* Ks = reinterpret_cast<const float*>(raw + AOFF_K);
    const float* Vs = reinterpret_cast<const float*>(raw + AOFF_V);
    const int c0 = w * 16;

    const float* qr = Qs + l * PAD + c0;
    ulonglong2 qa = *reinterpret_cast<const ulonglong2*>(qr);
    ulonglong2 qb = *reinterpret_cast<const ulonglong2*>(qr + 4);
    ulonglong2 qc = *reinterpret_cast<const ulonglong2*>(qr + 8);
    ulonglong2 qd = *reinterpret_cast<const ulonglong2*>(qr + 12);

    float sc[NPG];
    float mx = -1e30f;
#pragma unroll
    for (int j = 0; j < NPG; j++) {
        const float* kr = Ks + j * PAD + c0;
        ulonglong2 ka = *reinterpret_cast<const ulonglong2*>(kr);
        ulonglong2 kb = *reinterpret_cast<const ulonglong2*>(kr + 4);
        ulonglong2 kc = *reinterpret_cast<const ulonglong2*>(kr + 8);
        ulonglong2 kd = *reinterpret_cast<const ulonglong2*>(kr + 12);
        ull t2 = 0ULL;
        ffma2(t2, qa.x, ka.x); ffma2(t2, qa.y, ka.y);
        ffma2(t2, qb.x, kb.x); ffma2(t2, qb.y, kb.y);
        ffma2(t2, qc.x, kc.x); ffma2(t2, qc.y, kc.y);
        ffma2(t2, qd.x, kd.x); ffma2(t2, qd.y, kd.y);
        float tl, th; unpack2(t2, tl, th);
        const float t = tl + th;
        sc[j] = t;
        mx = fmaxf(mx, t);
    }
    float sum = 0.f;
#pragma unroll
    for (int j = 0; j < NPG; j++) { sc[j] = __expf(sc[j] - mx); sum += sc[j]; }
    const float inv = 1.0f / sum;

    ull o2[8];
#pragma unroll
    for (int i = 0; i < 8; i++) o2[i] = 0ULL;
#pragma unroll
    for (int j = 0; j < NPG; j++) {
        const ull p2 = pack2(sc[j], sc[j]);
        const float* vr = Vs + j * PAD + c0;
        ulonglong2 va = *reinterpret_cast<const ulonglong2*>(vr);
        ulonglong2 vb = *reinterpret_cast<const ulonglong2*>(vr + 4);
        ulonglong2 vc = *reinterpret_cast<const ulonglong2*>(vr + 8);
        ulonglong2 vd = *reinterpret_cast<const ulonglong2*>(vr + 12);
        ffma2(o2[0], p2, va.x); ffma2(o2[1], p2, va.y);
        ffma2(o2[2], p2, vb.x); ffma2(o2[3], p2, vb.y);
        ffma2(o2[4], p2, vc.x); ffma2(o2[5], p2, vc.y);
        ffma2(o2[6], p2, vd.x); ffma2(o2[7], p2, vd.y);
    }
    // write attention output as bf16 hi/lo directly into the pre-tiled A layout
    {
        unsigned char* tileb = g_ao + (size_t)(g >> 1) * ATILE;
        const int row = (g & 1) * 32 + l;
#pragma unroll
        for (int p = 0; p < 4; p++) {
            float x0, x1, x2, x3;
            unpack2(o2[2 * p],     x0, x1);
            unpack2(o2[2 * p + 1], x2, x3);
            float4 x = make_float4(x0 * inv, x1 * inv, x2 * inv, x3 * inv);
            ull hw, lw; split4(x, hw, lw);
            const int col = c0 + 4 * p;
            *(ull*)(tileb + row * XSB + col * 2)        = hw;
            *(ull*)(tileb + XH64 + row * XSB + col * 2) = lw;
        }
    }
}

// ---------- kernel 3: out projection, CTA = 64-row tile ----------
extern "C" __global__ void __launch_bounds__(TPB, 2)
outproj_kernel(const float* __restrict__ bo, float* __restrict__ out)
{
    extern __shared__ char raw[];
    const int tid = threadIdx.x;
    const int w = tid >> 5, l = tid & 31;
    const int m = blockIdx.x;
    const uint32_t sb = s2u(raw);
    float* bias_s = reinterpret_cast<float*>(raw + OFF_BIAS);

    copy_W_async(3, sb, tid);
    // copy pre-tiled A (34816 B = 2176 x 16B chunks)
    {
        const unsigned char* src = g_ao + (size_t)m * ATILE;
#pragma unroll
        for (int i = 0; i < 8; i++)
            cp16(sb + OFF_X + (i * TPB + tid) * 16, src + (size_t)(i * TPB + tid) * 16);
        if (tid < 128)
            cp16(sb + OFF_X + (2048 + tid) * 16, src + (size_t)(2048 + tid) * 16);
        CP_COMMIT();
    }
    if (tid < 128) bias_s[tid] = bo[tid];
    CP_WAIT0();
    __syncthreads();

    float acc[8][4];
    gemm8(raw, acc, w, l);
    epilogue8(acc, bias_s, 1.0f, out + (size_t)m * 64 * E_DIM, E_DIM, w, l);
}

extern "C" void kernel_launch(void* const* d_in, const int* in_sizes, int n_in,
                              void* d_out, int out_size)
{
    const float* query = (const float*)d_in[0];
    const float* key_  = (const float*)d_in[1];
    const float* value = (const float*)d_in[2];
    const float* wq    = (const float*)d_in[3];
    const float* wk    = (const float*)d_in[4];
    const float* wv    = (const float*)d_in[5];
    const float* bq    = (const float*)d_in[6];
    const float* bk    = (const float*)d_in[7];
    const float* bv    = (const float*)d_in[8];
    const float* wo    = (const float*)d_in[9];
    const float* bo    = (const float*)d_in[10];
    float* out = (float*)d_out;

    const int N  = in_sizes[0] / E_DIM;   // total nodes (32768)
    const int nm = N / 64;                // 64-row M-tiles (512)
    const int G  = N / NPG;               // graphs (1024)

    wconv_kernel<<<64, 256>>>(wq, wk, wv, wo);

    cudaFuncSetAttribute(proj_kernel,
                         cudaFuncAttributeMaxDynamicSharedMemorySize, SMEM_GEMM);
    cudaFuncSetAttribute(outproj_kernel,
                         cudaFuncAttributeMaxDynamicSharedMemorySize, SMEM_GEMM);
    cudaFuncSetAttribute(attn_kernel,
                         cudaFuncAttributeMaxDynamicSharedMemorySize, SMEM_ATTN);

    dim3 pgrid(nm, 3);
    proj_kernel<<<pgrid, TPB, SMEM_GEMM>>>(query, key_, value, bq, bk, bv);
    attn_kernel<<<G, TPB, SMEM_ATTN>>>();
    outproj_kernel<<<nm, TPB, SMEM_GEMM>>>(bo, out);
}

// round 14
// speedup vs baseline: 1.3452x; 1.3452x over previous
#include <cuda_runtime.h>
#include <cuda_fp16.h>
#include <cstdint>

typedef unsigned long long ull;

#define E_DIM 128
#define NPG   32
#define TPB   512
#define PAD   132           // fp32 row stride (floats)
#define XSB   272           // f16 A-tile row stride (bytes)
#define XH64  17408         // bytes per 64-row f16 tile (64*272)
#define WHALF 34816         // bytes per 128-row f16 tile (128*272)
#define WB    69632         // bytes per weight (hi+lo)

// smem byte offsets (same footprint as R6)
#define OFF_W    0          // 69632: current weight hi/lo (full K resident)
#define OFF_X    69632      // 34816 region: X hi tile; later V_s fp32 (33792)
#define OFF_C    104448     // 34816 region: Q_s fp32 (33792); later attn-out hi tile
#define OFF_D    139264     // 33792: K_s fp32
#define OFF_BIAS 173056     // 512 floats
#define SMEM_TOTAL 175104

__device__ __align__(1024) unsigned char g_wconv[4 * WB];

// ---------- helpers ----------
__device__ __forceinline__ uint32_t s2u(const void* p) {
    uint32_t a;
    asm("{ .reg .u64 t; cvta.to.shared.u64 t, %1; cvt.u32.u64 %0, t; }" : "=r"(a) : "l"(p));
    return a;
}
__device__ __forceinline__ ull pack2(float lo, float hi) {
    ull r; asm("mov.b64 %0, {%1, %2};" : "=l"(r) : "f"(lo), "f"(hi)); return r;
}
__device__ __forceinline__ void unpack2(ull p, float& lo, float& hi) {
    asm("mov.b64 {%0, %1}, %2;" : "=f"(lo), "=f"(hi) : "l"(p));
}
__device__ __forceinline__ void ffma2(ull& d, ull a, ull b) {
    asm("fma.rn.f32x2 %0, %1, %2, %0;" : "+l"(d) : "l"(a), "l"(b));
}
__device__ __forceinline__ ull pack4h(__half a, __half b, __half c, __half d) {
    uint32_t lo = ((uint32_t)__half_as_ushort(b) << 16) | __half_as_ushort(a);
    uint32_t hi = ((uint32_t)__half_as_ushort(d) << 16) | __half_as_ushort(c);
    return ((ull)hi << 32) | lo;
}
// fp16 hi/lo split of 4 floats (weights)
__device__ __forceinline__ void split4h(float4 x, ull& hiw, ull& low) {
    __half h0 = __float2half(x.x), h1 = __float2half(x.y),
           h2 = __float2half(x.z), h3 = __float2half(x.w);
    __half l0 = __float2half(x.x - __half2float(h0));
    __half l1 = __float2half(x.y - __half2float(h1));
    __half l2 = __float2half(x.z - __half2float(h2));
    __half l3 = __float2half(x.w - __half2float(h3));
    hiw = pack4h(h0, h1, h2, h3);
    low = pack4h(l0, l1, l2, l3);
}
// fp16 hi-only conversion of 4 floats (activations)
__device__ __forceinline__ ull cvt4h(float4 x) {
    return pack4h(__float2half(x.x), __float2half(x.y),
                  __float2half(x.z), __float2half(x.w));
}
__device__ __forceinline__ void ldsm4(uint32_t& r0, uint32_t& r1, uint32_t& r2,
                                      uint32_t& r3, uint32_t a) {
    asm volatile("ldmatrix.sync.aligned.m8n8.x4.shared.b16 {%0,%1,%2,%3}, [%4];"
                 : "=r"(r0), "=r"(r1), "=r"(r2), "=r"(r3) : "r"(a));
}
__device__ __forceinline__ void mma_f16(float* c, const uint32_t* a,
                                        uint32_t b0, uint32_t b1) {
    asm volatile(
        "mma.sync.aligned.m16n8k16.row.col.f32.f16.f16.f32 "
        "{%0,%1,%2,%3}, {%4,%5,%6,%7}, {%8,%9}, {%0,%1,%2,%3};"
        : "+f"(c[0]), "+f"(c[1]), "+f"(c[2]), "+f"(c[3])
        : "r"(a[0]), "r"(a[1]), "r"(a[2]), "r"(a[3]), "r"(b0), "r"(b1));
}
__device__ __forceinline__ void cp16(uint32_t smem, const void* g) {
    asm volatile("cp.async.ca.shared.global [%0], [%1], 16;" :: "r"(smem), "l"(g) : "memory");
}
#define CP_COMMIT() asm volatile("cp.async.commit_group;" ::: "memory")
#define CP_WAIT0()  asm volatile("cp.async.wait_group 0;" ::: "memory")

// ---------- building blocks ----------
// X (64x128 f32, gmem) -> fp16 hi tile at OFF_X (512 threads)
__device__ __forceinline__ void convert_X(const float* __restrict__ gx, char* raw, int tid) {
    const int row  = tid >> 3;           // 0..63
    const int colb = (tid & 7) * 16;
#pragma unroll
    for (int i = 0; i < 4; i++) {
        const int col = colb + i * 4;
        float4 x = *reinterpret_cast<const float4*>(gx + row * E_DIM + col);
        *(ull*)(raw + OFF_X + row * XSB + col * 2) = cvt4h(x);
    }
}
// async full weight copy: 4352 x 16B = 69632B
__device__ __forceinline__ void copy_W_async(int wsel, uint32_t sb, int tid) {
    const char* s = reinterpret_cast<const char*>(g_wconv) + wsel * WB;
    const uint32_t d = sb + OFF_W;
#pragma unroll
    for (int i = 0; i < 8; i++)
        cp16(d + (i * TPB + tid) * 16, s + (size_t)(i * TPB + tid) * 16);
    if (tid < 256)
        cp16(d + (4096 + tid) * 16, s + (size_t)(4096 + tid) * 16);
    CP_COMMIT();
}

// 64x128 output, K=128, fp16 2-term MMA (Ahi*Bhi + Ahi*Blo).
// Per k8 step: 4 ldsm4 -> 8 MMAs. Warp tile 16x32 (4x4 warp grid, 16 warps).
__device__ __forceinline__ void gemm_compute(char* raw, int offA, float acc[4][4],
                                             int w, int l) {
    const int wm = w >> 2, wn = w & 3;
    const uint32_t sb = s2u(raw);
#pragma unroll
    for (int s = 0; s < 4; s++)
#pragma unroll
        for (int i = 0; i < 4; i++) acc[s][i] = 0.f;
    const uint32_t aBase = sb + offA + (wm * 16 + (l & 15)) * XSB + (l >> 4) * 16;
    const uint32_t bBase = sb + OFF_W +
        (wn * 32 + (l & 7) + ((l >> 4) & 1) * 8) * XSB + ((l >> 3) & 1) * 16;
#pragma unroll
    for (int k8 = 0; k8 < 8; k8++) {
        uint32_t ah[4];
        ldsm4(ah[0], ah[1], ah[2], ah[3], aBase + k8 * 32);
        uint32_t bh[8], bl[8];
        ldsm4(bh[0], bh[1], bh[2], bh[3], bBase + k8 * 32);              // subs 0,1
        ldsm4(bh[4], bh[5], bh[6], bh[7], bBase + 16 * XSB + k8 * 32);   // subs 2,3
        ldsm4(bl[0], bl[1], bl[2], bl[3], bBase + WHALF + k8 * 32);
        ldsm4(bl[4], bl[5], bl[6], bl[7], bBase + WHALF + 16 * XSB + k8 * 32);
#pragma unroll
        for (int sub = 0; sub < 4; sub++)
            mma_f16(acc[sub], ah, bh[2 * sub], bh[2 * sub + 1]);   // hi*hi
#pragma unroll
        for (int sub = 0; sub < 4; sub++)
            mma_f16(acc[sub], ah, bl[2 * sub], bl[2 * sub + 1]);   // hi*lo
    }
}
__device__ __forceinline__ void epilogue(const float acc[4][4], const float* bias,
                                         float scale, float* dst, int dstride,
                                         int w, int l) {
    const int wm = w >> 2, wn = w & 3;
    const int r0 = wm * 16 + (l >> 2);
#pragma unroll
    for (int sub = 0; sub < 4; sub++) {
        const int cb = wn * 32 + sub * 8 + (l & 3) * 2;
        float2 v;
        v.x = (acc[sub][0] + bias[cb]) * scale;
        v.y = (acc[sub][1] + bias[cb + 1]) * scale;
        *reinterpret_cast<float2*>(dst + r0 * dstride + cb) = v;
        v.x = (acc[sub][2] + bias[cb]) * scale;
        v.y = (acc[sub][3] + bias[cb + 1]) * scale;
        *reinterpret_cast<float2*>(dst + (r0 + 8) * dstride + cb) = v;
    }
}

// ---------- pre-kernel: weights f32 -> fp16 hi/lo tiles in g_wconv ----------
extern "C" __global__ void wconv_kernel(const float* __restrict__ wq,
                                        const float* __restrict__ wk,
                                        const float* __restrict__ wv,
                                        const float* __restrict__ wo) {
    const int idx = (blockIdx.x * blockDim.x + threadIdx.x) * 4;
    const int wsel = idx >> 14;
    const float* W = (wsel == 0) ? wq : (wsel == 1) ? wk : (wsel == 2) ? wv : wo;
    const int rem = idx & 16383;
    const int c = rem >> 7, k = rem & 127;
    float4 x = *reinterpret_cast<const float4*>(W + c * 128 + k);
    ull hw, lw; split4h(x, hw, lw);
    *(ull*)(g_wconv + wsel * WB + c * XSB + k * 2)         = hw;
    *(ull*)(g_wconv + wsel * WB + WHALF + c * XSB + k * 2) = lw;
}

// ---------- main fused kernel: 2 graphs per CTA, 16 warps ----------
extern "C" __global__ void __launch_bounds__(TPB, 1)
iattn_h2_kernel(const float* __restrict__ query, const float* __restrict__ key,
                const float* __restrict__ value,
                const float* __restrict__ bq, const float* __restrict__ bk,
                const float* __restrict__ bv, const float* __restrict__ bo,
                float* __restrict__ out)
{
    extern __shared__ char raw[];
    const int tid = threadIdx.x;
    const int w = tid >> 5, l = tid & 31;
    const size_t base = (size_t)blockIdx.x * 64 * E_DIM;
    const uint32_t sb = s2u(raw);
    float* bias_s = reinterpret_cast<float*>(raw + OFF_BIAS);

    copy_W_async(0, sb, tid);          // Wq copy overlaps bias + convert
    {
        const float* bsrc = (tid < 128) ? bq : (tid < 256) ? bk : (tid < 384) ? bv : bo;
        bias_s[tid] = bsrc[tid & 127];
    }

    float acc[4][4];

    // --- Q projection -> Q_s (fp32, OFF_C) ---
    convert_X(query + base, raw, tid);
    CP_WAIT0();
    __syncthreads();
    gemm_compute(raw, OFF_X, acc, w, l);
    epilogue(acc, bias_s, 0.25f, reinterpret_cast<float*>(raw + OFF_C), PAD, w, l);
    __syncthreads();

    // --- K projection -> K_s (fp32, OFF_D) ---
    copy_W_async(1, sb, tid);
    convert_X(key + base, raw, tid);
    CP_WAIT0();
    __syncthreads();
    gemm_compute(raw, OFF_X, acc, w, l);
    epilogue(acc, bias_s + 128, 1.0f, reinterpret_cast<float*>(raw + OFF_D), PAD, w, l);
    __syncthreads();

    // --- V projection -> V_s (fp32, overlays X region) ---
    copy_W_async(2, sb, tid);
    convert_X(value + base, raw, tid);
    CP_WAIT0();
    __syncthreads();
    gemm_compute(raw, OFF_X, acc, w, l);
    __syncthreads();   // all ldmatrix reads of Xv/Wv done before overlay
    epilogue(acc, bias_s + 256, 1.0f, reinterpret_cast<float*>(raw + OFF_X), PAD, w, l);
    copy_W_async(3, sb, tid);   // Wo (W region dead after sync above)
    CP_WAIT0();
    __syncthreads();            // V_s + Wo visible

    // --- attention: warp w -> graph g=w>>3, head h=w&7 ---
    {
        const float* Qs = reinterpret_cast<const float*>(raw + OFF_C);
        const float* Ks = reinterpret_cast<const float*>(raw + OFF_D);
        const float* Vs = reinterpret_cast<const float*>(raw + OFF_X);
        const int g = w >> 3;
        const int h = w & 7;
        const int c0 = h * 16;
        const int row = g * NPG + l;

        const float* qr = Qs + row * PAD + c0;
        ulonglong2 qa = *reinterpret_cast<const ulonglong2*>(qr);
        ulonglong2 qb = *reinterpret_cast<const ulonglong2*>(qr + 4);
        ulonglong2 qc = *reinterpret_cast<const ulonglong2*>(qr + 8);
        ulonglong2 qd = *reinterpret_cast<const ulonglong2*>(qr + 12);

        float sc[NPG];
        float mx = -1e30f;
#pragma unroll
        for (int j = 0; j < NPG; j++) {
            const float* kr = Ks + (g * NPG + j) * PAD + c0;
            ulonglong2 ka = *reinterpret_cast<const ulonglong2*>(kr);
            ulonglong2 kb = *reinterpret_cast<const ulonglong2*>(kr + 4);
            ulonglong2 kc = *reinterpret_cast<const ulonglong2*>(kr + 8);
            ulonglong2 kd = *reinterpret_cast<const ulonglong2*>(kr + 12);
            ull t2 = 0ULL;
            ffma2(t2, qa.x, ka.x); ffma2(t2, qa.y, ka.y);
            ffma2(t2, qb.x, kb.x); ffma2(t2, qb.y, kb.y);
            ffma2(t2, qc.x, kc.x); ffma2(t2, qc.y, kc.y);
            ffma2(t2, qd.x, kd.x); ffma2(t2, qd.y, kd.y);
            float tl, th; unpack2(t2, tl, th);
            const float t = tl + th;
            sc[j] = t;
            mx = fmaxf(mx, t);
        }
        float sum = 0.f;
#pragma unroll
        for (int j = 0; j < NPG; j++) { sc[j] = __expf(sc[j] - mx); sum += sc[j]; }
        const float inv = 1.0f / sum;

        ull o2[8];
#pragma unroll
        for (int i = 0; i < 8; i++) o2[i] = 0ULL;
#pragma unroll
        for (int j = 0; j < NPG; j++) {
            const ull p2 = pack2(sc[j], sc[j]);
            const float* vr = Vs + (g * NPG + j) * PAD + c0;
            ulonglong2 va = *reinterpret_cast<const ulonglong2*>(vr);
            ulonglong2 vb = *reinterpret_cast<const ulonglong2*>(vr + 4);
            ulonglong2 vc = *reinterpret_cast<const ulonglong2*>(vr + 8);
            ulonglong2 vd = *reinterpret_cast<const ulonglong2*>(vr + 12);
            ffma2(o2[0], p2, va.x); ffma2(o2[1], p2, va.y);
            ffma2(o2[2], p2, vb.x); ffma2(o2[3], p2, vb.y);
            ffma2(o2[4], p2, vc.x); ffma2(o2[5], p2, vc.y);
            ffma2(o2[6], p2, vd.x); ffma2(o2[7], p2, vd.y);
        }
        __syncthreads();   // all warps done reading Q_s before overlaying OFF_C
        // write attention output as fp16 hi tile into OFF_C
#pragma unroll
        for (int p = 0; p < 4; p++) {
            float x0, x1, x2, x3;
            unpack2(o2[2 * p],     x0, x1);
            unpack2(o2[2 * p + 1], x2, x3);
            float4 x = make_float4(x0 * inv, x1 * inv, x2 * inv, x3 * inv);
            const int col = c0 + 4 * p;
            *(ull*)(raw + OFF_C + row * XSB + col * 2) = cvt4h(x);
        }
    }
    __syncthreads();   // attn-out tile complete

    // --- out projection -> gmem ---
    gemm_compute(raw, OFF_C, acc, w, l);
    epilogue(acc, bias_s + 384, 1.0f, out + base, E_DIM, w, l);
}

extern "C" void kernel_launch(void* const* d_in, const int* in_sizes, int n_in,
                              void* d_out, int out_size)
{
    const float* query = (const float*)d_in[0];
    const float* key_  = (const float*)d_in[1];
    const float* value = (const float*)d_in[2];
    const float* wq    = (const float*)d_in[3];
    const float* wk    = (const float*)d_in[4];
    const float* wv    = (const float*)d_in[5];
    const float* bq    = (const float*)d_in[6];
    const float* bk    = (const float*)d_in[7];
    const float* bv    = (const float*)d_in[8];
    const float* wo    = (const float*)d_in[9];
    const float* bo    = (const float*)d_in[10];
    float* out = (float*)d_out;

    const int N = in_sizes[0] / E_DIM;   // total nodes
    const int grid = N / 64;             // 2 graphs per CTA

    wconv_kernel<<<64, 256>>>(wq, wk, wv, wo);

    cudaFuncSetAttribute(iattn_h2_kernel,
                         cudaFuncAttributeMaxDynamicSharedMemorySize, SMEM_TOTAL);
    iattn_h2_kernel<<<grid, TPB, SMEM_TOTAL>>>(
        query, key_, value, bq, bk, bv, bo, out);
}

// round 15
// speedup vs baseline: 1.3463x; 1.0008x over previous
#include <cuda_runtime.h>
#include <cuda_fp16.h>
#include <cstdint>

typedef unsigned long long ull;

#define E_DIM 128
#define NPG   32
#define TPB   512
#define PAD   132           // fp32 row stride (floats)
#define XSB   272           // f16 A-tile row stride (bytes)
#define XH64  17408         // bytes per 64-row f16 tile (64*272)
#define WHALF 34816         // bytes per 128-row f16 tile (128*272)
#define WB    69632         // bytes per weight (hi+lo)

// smem byte offsets (same footprint as R14)
#define OFF_W    0          // 69632: current weight hi/lo (full K resident)
#define OFF_X    69632      // 34816 region: X hi tile; later V_s fp32 (33792)
#define OFF_C    104448     // 34816 region: Q_s fp32 (33792); later attn-out hi tile
#define OFF_D    139264     // 33792: K_s fp32
#define OFF_BIAS 173056     // 512 floats
#define SMEM_TOTAL 175104

__device__ __align__(1024) unsigned char g_wconv[4 * WB];

// ---------- helpers ----------
__device__ __forceinline__ uint32_t s2u(const void* p) {
    uint32_t a;
    asm("{ .reg .u64 t; cvta.to.shared.u64 t, %1; cvt.u32.u64 %0, t; }" : "=r"(a) : "l"(p));
    return a;
}
__device__ __forceinline__ ull pack2(float lo, float hi) {
    ull r; asm("mov.b64 %0, {%1, %2};" : "=l"(r) : "f"(lo), "f"(hi)); return r;
}
__device__ __forceinline__ void unpack2(ull p, float& lo, float& hi) {
    asm("mov.b64 {%0, %1}, %2;" : "=f"(lo), "=f"(hi) : "l"(p));
}
__device__ __forceinline__ void ffma2(ull& d, ull a, ull b) {
    asm("fma.rn.f32x2 %0, %1, %2, %0;" : "+l"(d) : "l"(a), "l"(b));
}
__device__ __forceinline__ ull pack4h(__half a, __half b, __half c, __half d) {
    uint32_t lo = ((uint32_t)__half_as_ushort(b) << 16) | __half_as_ushort(a);
    uint32_t hi = ((uint32_t)__half_as_ushort(d) << 16) | __half_as_ushort(c);
    return ((ull)hi << 32) | lo;
}
__device__ __forceinline__ void split4h(float4 x, ull& hiw, ull& low) {
    __half h0 = __float2half(x.x), h1 = __float2half(x.y),
           h2 = __float2half(x.z), h3 = __float2half(x.w);
    __half l0 = __float2half(x.x - __half2float(h0));
    __half l1 = __float2half(x.y - __half2float(h1));
    __half l2 = __float2half(x.z - __half2float(h2));
    __half l3 = __float2half(x.w - __half2float(h3));
    hiw = pack4h(h0, h1, h2, h3);
    low = pack4h(l0, l1, l2, l3);
}
__device__ __forceinline__ ull cvt4h(float4 x) {
    return pack4h(__float2half(x.x), __float2half(x.y),
                  __float2half(x.z), __float2half(x.w));
}
__device__ __forceinline__ void ldsm4(uint32_t& r0, uint32_t& r1, uint32_t& r2,
                                      uint32_t& r3, uint32_t a) {
    asm volatile("ldmatrix.sync.aligned.m8n8.x4.shared.b16 {%0,%1,%2,%3}, [%4];"
                 : "=r"(r0), "=r"(r1), "=r"(r2), "=r"(r3) : "r"(a));
}
__device__ __forceinline__ void mma_f16(float* c, const uint32_t* a,
                                        uint32_t b0, uint32_t b1) {
    asm volatile(
        "mma.sync.aligned.m16n8k16.row.col.f32.f16.f16.f32 "
        "{%0,%1,%2,%3}, {%4,%5,%6,%7}, {%8,%9}, {%0,%1,%2,%3};"
        : "+f"(c[0]), "+f"(c[1]), "+f"(c[2]), "+f"(c[3])
        : "r"(a[0]), "r"(a[1]), "r"(a[2]), "r"(a[3]), "r"(b0), "r"(b1));
}
__device__ __forceinline__ void cp16(uint32_t smem, const void* g) {
    asm volatile("cp.async.ca.shared.global [%0], [%1], 16;" :: "r"(smem), "l"(g) : "memory");
}
#define CP_COMMIT() asm volatile("cp.async.commit_group;" ::: "memory")
#define CP_WAIT0()  asm volatile("cp.async.wait_group 0;" ::: "memory")

// ---------- building blocks ----------
__device__ __forceinline__ void convert_X(const float* __restrict__ gx, char* raw, int tid) {
    const int row  = tid >> 3;           // 0..63
    const int colb = (tid & 7) * 16;
#pragma unroll
    for (int i = 0; i < 4; i++) {
        const int col = colb + i * 4;
        float4 x = *reinterpret_cast<const float4*>(gx + row * E_DIM + col);
        *(ull*)(raw + OFF_X + row * XSB + col * 2) = cvt4h(x);
    }
}
__device__ __forceinline__ void copy_W_async(int wsel, uint32_t sb, int tid) {
    const char* s = reinterpret_cast<const char*>(g_wconv) + wsel * WB;
    const uint32_t d = sb + OFF_W;
#pragma unroll
    for (int i = 0; i < 8; i++)
        cp16(d + (i * TPB + tid) * 16, s + (size_t)(i * TPB + tid) * 16);
    if (tid < 256)
        cp16(d + (4096 + tid) * 16, s + (size_t)(4096 + tid) * 16);
    CP_COMMIT();
}

// 64x128 output, K=128, fp16 2-term MMA, software-pipelined fragments.
// Per k8: issue k8+1's 4 ldsm4 BEFORE k8's 8 MMAs (ldsm->use distance ~1 iter).
__device__ __forceinline__ void gemm_compute(char* raw, int offA, float acc[4][4],
                                             int w, int l) {
    const int wm = w >> 2, wn = w & 3;
    const uint32_t sb = s2u(raw);
#pragma unroll
    for (int s = 0; s < 4; s++)
#pragma unroll
        for (int i = 0; i < 4; i++) acc[s][i] = 0.f;
    const uint32_t aBase = sb + offA + (wm * 16 + (l & 15)) * XSB + (l >> 4) * 16;
    const uint32_t bBase = sb + OFF_W +
        (wn * 32 + (l & 7) + ((l >> 4) & 1) * 8) * XSB + ((l >> 3) & 1) * 16;

    uint32_t ah[2][4], bh[2][8], bl[2][8];
    // prologue: load k8 = 0 into buffer 0
    ldsm4(ah[0][0], ah[0][1], ah[0][2], ah[0][3], aBase);
    ldsm4(bh[0][0], bh[0][1], bh[0][2], bh[0][3], bBase);
    ldsm4(bh[0][4], bh[0][5], bh[0][6], bh[0][7], bBase + 16 * XSB);
    ldsm4(bl[0][0], bl[0][1], bl[0][2], bl[0][3], bBase + WHALF);
    ldsm4(bl[0][4], bl[0][5], bl[0][6], bl[0][7], bBase + WHALF + 16 * XSB);

#pragma unroll
    for (int k8 = 0; k8 < 8; k8++) {
        const int cur = k8 & 1, nxt = cur ^ 1;
        if (k8 < 7) {
            const uint32_t ko = (k8 + 1) * 32;
            ldsm4(ah[nxt][0], ah[nxt][1], ah[nxt][2], ah[nxt][3], aBase + ko);
            ldsm4(bh[nxt][0], bh[nxt][1], bh[nxt][2], bh[nxt][3], bBase + ko);
            ldsm4(bh[nxt][4], bh[nxt][5], bh[nxt][6], bh[nxt][7], bBase + 16 * XSB + ko);
            ldsm4(bl[nxt][0], bl[nxt][1], bl[nxt][2], bl[nxt][3], bBase + WHALF + ko);
            ldsm4(bl[nxt][4], bl[nxt][5], bl[nxt][6], bl[nxt][7],
                  bBase + WHALF + 16 * XSB + ko);
        }
#pragma unroll
        for (int sub = 0; sub < 4; sub++)
            mma_f16(acc[sub], ah[cur], bh[cur][2 * sub], bh[cur][2 * sub + 1]);  // hi*hi
#pragma unroll
        for (int sub = 0; sub < 4; sub++)
            mma_f16(acc[sub], ah[cur], bl[cur][2 * sub], bl[cur][2 * sub + 1]);  // hi*lo
    }
}
__device__ __forceinline__ void epilogue(const float acc[4][4], const float* bias,
                                         float scale, float* dst, int dstride,
                                         int w, int l) {
    const int wm = w >> 2, wn = w & 3;
    const int r0 = wm * 16 + (l >> 2);
#pragma unroll
    for (int sub = 0; sub < 4; sub++) {
        const int cb = wn * 32 + sub * 8 + (l & 3) * 2;
        float2 v;
        v.x = (acc[sub][0] + bias[cb]) * scale;
        v.y = (acc[sub][1] + bias[cb + 1]) * scale;
        *reinterpret_cast<float2*>(dst + r0 * dstride + cb) = v;
        v.x = (acc[sub][2] + bias[cb]) * scale;
        v.y = (acc[sub][3] + bias[cb + 1]) * scale;
        *reinterpret_cast<float2*>(dst + (r0 + 8) * dstride + cb) = v;
    }
}

// ---------- pre-kernel: weights f32 -> fp16 hi/lo tiles in g_wconv ----------
extern "C" __global__ void wconv_kernel(const float* __restrict__ wq,
                                        const float* __restrict__ wk,
                                        const float* __restrict__ wv,
                                        const float* __restrict__ wo) {
    const int idx = (blockIdx.x * blockDim.x + threadIdx.x) * 4;
    const int wsel = idx >> 14;
    const float* W = (wsel == 0) ? wq : (wsel == 1) ? wk : (wsel == 2) ? wv : wo;
    const int rem = idx & 16383;
    const int c = rem >> 7, k = rem & 127;
    float4 x = *reinterpret_cast<const float4*>(W + c * 128 + k);
    ull hw, lw; split4h(x, hw, lw);
    *(ull*)(g_wconv + wsel * WB + c * XSB + k * 2)         = hw;
    *(ull*)(g_wconv + wsel * WB + WHALF + c * XSB + k * 2) = lw;
}

// ---------- main fused kernel: 2 graphs per CTA, 16 warps ----------
extern "C" __global__ void __launch_bounds__(TPB, 1)
iattn_h3_kernel(const float* __restrict__ query, const float* __restrict__ key,
                const float* __restrict__ value,
                const float* __restrict__ bq, const float* __restrict__ bk,
                const float* __restrict__ bv, const float* __restrict__ bo,
                float* __restrict__ out)
{
    extern __shared__ char raw[];
    const int tid = threadIdx.x;
    const int w = tid >> 5, l = tid & 31;
    const size_t base = (size_t)blockIdx.x * 64 * E_DIM;
    const uint32_t sb = s2u(raw);
    float* bias_s = reinterpret_cast<float*>(raw + OFF_BIAS);

    copy_W_async(0, sb, tid);
    {
        const float* bsrc = (tid < 128) ? bq : (tid < 256) ? bk : (tid < 384) ? bv : bo;
        bias_s[tid] = bsrc[tid & 127];
    }

    float acc[4][4];

    // --- Q projection -> Q_s (fp32, OFF_C) ---
    convert_X(query + base, raw, tid);
    CP_WAIT0();
    __syncthreads();
    gemm_compute(raw, OFF_X, acc, w, l);
    epilogue(acc, bias_s, 0.25f, reinterpret_cast<float*>(raw + OFF_C), PAD, w, l);
    __syncthreads();

    // --- K projection -> K_s (fp32, OFF_D) ---
    copy_W_async(1, sb, tid);
    convert_X(key + base, raw, tid);
    CP_WAIT0();
    __syncthreads();
    gemm_compute(raw, OFF_X, acc, w, l);
    epilogue(acc, bias_s + 128, 1.0f, reinterpret_cast<float*>(raw + OFF_D), PAD, w, l);
    __syncthreads();

    // --- V projection -> V_s (fp32, overlays X region) ---
    copy_W_async(2, sb, tid);
    convert_X(value + base, raw, tid);
    CP_WAIT0();
    __syncthreads();
    gemm_compute(raw, OFF_X, acc, w, l);
    __syncthreads();   // all ldmatrix reads of Xv/Wv done before overlay
    epilogue(acc, bias_s + 256, 1.0f, reinterpret_cast<float*>(raw + OFF_X), PAD, w, l);
    copy_W_async(3, sb, tid);   // Wo (W region dead after sync above)
    CP_WAIT0();
    __syncthreads();            // V_s + Wo visible

    // --- attention: warp w -> graph g=w>>3, head h=w&7 ---
    {
        const float* Qs = reinterpret_cast<const float*>(raw + OFF_C);
        const float* Ks = reinterpret_cast<const float*>(raw + OFF_D);
        const float* Vs = reinterpret_cast<const float*>(raw + OFF_X);
        const int g = w >> 3;
        const int h = w & 7;
        const int c0 = h * 16;
        const int row = g * NPG + l;

        const float* qr = Qs + row * PAD + c0;
        ulonglong2 qa = *reinterpret_cast<const ulonglong2*>(qr);
        ulonglong2 qb = *reinterpret_cast<const ulonglong2*>(qr + 4);
        ulonglong2 qc = *reinterpret_cast<const ulonglong2*>(qr + 8);
        ulonglong2 qd = *reinterpret_cast<const ulonglong2*>(qr + 12);

        float sc[NPG];
        float mx = -1e30f;
#pragma unroll
        for (int j = 0; j < NPG; j++) {
            const float* kr = Ks + (g * NPG + j) * PAD + c0;
            ulonglong2 ka = *reinterpret_cast<const ulonglong2*>(kr);
            ulonglong2 kb = *reinterpret_cast<const ulonglong2*>(kr + 4);
            ulonglong2 kc = *reinterpret_cast<const ulonglong2*>(kr + 8);
            ulonglong2 kd = *reinterpret_cast<const ulonglong2*>(kr + 12);
            ull t2 = 0ULL;
            ffma2(t2, qa.x, ka.x); ffma2(t2, qa.y, ka.y);
            ffma2(t2, qb.x, kb.x); ffma2(t2, qb.y, kb.y);
            ffma2(t2, qc.x, kc.x); ffma2(t2, qc.y, kc.y);
            ffma2(t2, qd.x, kd.x); ffma2(t2, qd.y, kd.y);
            float tl, th; unpack2(t2, tl, th);
            const float t = tl + th;
            sc[j] = t;
            mx = fmaxf(mx, t);
        }
        float sum = 0.f;
#pragma unroll
        for (int j = 0; j < NPG; j++) { sc[j] = __expf(sc[j] - mx); sum += sc[j]; }
        const float inv = 1.0f / sum;

        ull o2[8];
#pragma unroll
        for (int i = 0; i < 8; i++) o2[i] = 0ULL;
#pragma unroll
        for (int j = 0; j < NPG; j++) {
            const ull p2 = pack2(sc[j], sc[j]);
            const float* vr = Vs + (g * NPG + j) * PAD + c0;
            ulonglong2 va = *reinterpret_cast<const ulonglong2*>(vr);
            ulonglong2 vb = *reinterpret_cast<const ulonglong2*>(vr + 4);
            ulonglong2 vc = *reinterpret_cast<const ulonglong2*>(vr + 8);
            ulonglong2 vd = *reinterpret_cast<const ulonglong2*>(vr + 12);
            ffma2(o2[0], p2, va.x); ffma2(o2[1], p2, va.y);
            ffma2(o2[2], p2, vb.x); ffma2(o2[3], p2, vb.y);
            ffma2(o2[4], p2, vc.x); ffma2(o2[5], p2, vc.y);
            ffma2(o2[6], p2, vd.x); ffma2(o2[7], p2, vd.y);
        }
        __syncthreads();   // all warps done reading Q_s before overlaying OFF_C
#pragma unroll
        for (int p = 0; p < 4; p++) {
            float x0, x1, x2, x3;
            unpack2(o2[2 * p],     x0, x1);
            unpack2(o2[2 * p + 1], x2, x3);
            float4 x = make_float4(x0 * inv, x1 * inv, x2 * inv, x3 * inv);
            const int col = c0 + 4 * p;
            *(ull*)(raw + OFF_C + row * XSB + col * 2) = cvt4h(x);
        }
    }
    __syncthreads();   // attn-out tile complete

    // --- out projection -> gmem ---
    gemm_compute(raw, OFF_C, acc, w, l);
    epilogue(acc, bias_s + 384, 1.0f, out + base, E_DIM, w, l);
}

extern "C" void kernel_launch(void* const* d_in, const int* in_sizes, int n_in,
                              void* d_out, int out_size)
{
    const float* query = (const float*)d_in[0];
    const float* key_  = (const float*)d_in[1];
    const float* value = (const float*)d_in[2];
    const float* wq    = (const float*)d_in[3];
    const float* wk    = (const float*)d_in[4];
    const float* wv    = (const float*)d_in[5];
    const float* bq    = (const float*)d_in[6];
    const float* bk    = (const float*)d_in[7];
    const float* bv    = (const float*)d_in[8];
    const float* wo    = (const float*)d_in[9];
    const float* bo    = (const float*)d_in[10];
    float* out = (float*)d_out;

    const int N = in_sizes[0] / E_DIM;   // total nodes
    const int grid = N / 64;             // 2 graphs per CTA

    wconv_kernel<<<64, 256>>>(wq, wk, wv, wo);

    cudaFuncSetAttribute(iattn_h3_kernel,
                         cudaFuncAttributeMaxDynamicSharedMemorySize, SMEM_TOTAL);
    iattn_h3_kernel<<<grid, TPB, SMEM_TOTAL>>>(
        query, key_, value, bq, bk, bv, bo, out);
}